// round 15
// baseline (speedup 1.0000x reference)
#include <cuda_runtime.h>
#include <cuda_bf16.h>
#include <cuda_fp8.h>
#include <math.h>
#include <stdint.h>

#define Bz   2
#define Nn   1024
#define Hh   768
#define Ss   30285
#define Kk   409
#define MAXW 30
#define WD   20
#define NBLK 6
#define MTILES64 947              // ceil(Bz*Ss/64)
#define CAP  1024
#define KEXT (Kk + 512)
#define WXY_OFF (1536*768)
#define WW_ROW 2304
#define WBLK (768*768)

// ---- mma_main smem layout (bytes), fp8, M=64 ----
#define SAFB  784                 // A row stride bytes
#define A_BYTES (64*SAFB)         // 50176
#define SBB   80                  // B row stride bytes
#define BSTG_BYTES (128*SBB)      // 10240 per stage
#define NSTG  3
#define B_OFF A_BYTES
#define RED_OFF B_OFF             // red aliases B region (post-loop only)
#define XO_OFF (A_BYTES + NSTG*BSTG_BYTES)   // 80896
#define YO_OFF (XO_OFF + 256)
#define RO_OFF (YO_OFF + 256)
#define DYNSMEM (RO_OFF + 256)               // 81664  -> 2 CTAs/SM

#define ASCALE 8.0f
#define INVSCALE (1.0f/512.0f)

__device__ __forceinline__ float gelu_exact(float x) {
    return 0.5f * x * (1.0f + erff(x * 0.70710678118654752f));
}
__device__ __forceinline__ float gelu_fast(float x) {
    float arg = 0.7978845608028654f * (x + 0.044715f * x * x * x);
    float th;
    asm("tanh.approx.f32 %0, %1;" : "=f"(th) : "f"(arg));
    return 0.5f * x * (1.0f + th);
}
__device__ __forceinline__ uint32_t smem_u32(const void* p) {
    uint32_t a;
    asm("{ .reg .u64 t; cvta.to.shared.u64 t, %1; cvt.u32.u64 %0, t; }" : "=r"(a) : "l"(p));
    return a;
}
__device__ __forceinline__ void cp_async16(uint32_t dst, const void* src) {
    asm volatile("cp.async.cg.shared.global [%0], [%1], 16;" :: "r"(dst), "l"(src));
}
#define CP_COMMIT() asm volatile("cp.async.commit_group;" ::: "memory")
#define CP_WAIT0()  asm volatile("cp.async.wait_group 0;" ::: "memory")
#define CP_WAIT1()  asm volatile("cp.async.wait_group 1;" ::: "memory")

__device__ __forceinline__ void mma16832(float* c, const unsigned* a, const unsigned* b) {
    asm volatile("mma.sync.aligned.m16n8k32.row.col.f32.e4m3.e4m3.f32 "
        "{%0,%1,%2,%3}, {%4,%5,%6,%7}, {%8,%9}, {%0,%1,%2,%3};"
        : "+f"(c[0]), "+f"(c[1]), "+f"(c[2]), "+f"(c[3])
        : "r"(a[0]), "r"(a[1]), "r"(a[2]), "r"(a[3]), "r"(b[0]), "r"(b[1]));
}
__device__ __forceinline__ void ldsm4(unsigned* r, uint32_t addr) {
    asm volatile("ldmatrix.sync.aligned.m8n8.x4.shared.b16 {%0,%1,%2,%3}, [%4];"
        : "=r"(r[0]), "=r"(r[1]), "=r"(r[2]), "=r"(r[3]) : "r"(addr));
}

// ---------------- scratch ----------------
__device__ unsigned char g_W8[768*768]; // e4m3(Wxy * 64) transposed [n][k]
__device__ float    g_P[Bz*Nn*Hh];
__device__ float    g_Q[Bz*Nn*Hh];
__device__ float    g_R[MAXW*Hh];
__device__ float    g_part2[NBLK*2*CAP];
__device__ float    g_Hc[(size_t)Bz*CAP*Hh];
__device__ float    g_scores[Bz*Ss];
__device__ unsigned g_keys[Bz*Ss];
__device__ int      g_len[Bz];
__device__ unsigned g_thr[Bz];
__device__ int      g_cand[Bz*CAP];
__device__ int      g_nc[Bz];
__device__ int      g_sel[Bz*Kk];
__device__ int      g_slot[Bz*Kk];

// ---------------- R[w] = width_emb[w] @ Ww + b1 ----------------
__global__ void r_kernel(const float* __restrict__ wemb,
                         const float* __restrict__ W1,
                         const float* __restrict__ b1) {
    int w = blockIdx.x;
    for (int c = threadIdx.x; c < Hh; c += blockDim.x) {
        float a = b1[c];
        #pragma unroll
        for (int j = 0; j < WD; j++) a += wemb[w*WD + j] * W1[(WW_ROW + j)*Hh + c];
        g_R[w*Hh + c] = a;
    }
}

// ---------------- Wxy -> transposed e4m3 (x64) + (fused) lengths ----------------
__global__ void prep2_kernel(const float* __restrict__ W1, const int* __restrict__ mask) {
    __shared__ float tile[32][33];
    int tx = threadIdx.x, ty = threadIdx.y;   // 32 x 8
    if (blockIdx.y == 24) {
        if (blockIdx.x >= Bz) return;
        __shared__ int red[256];
        int b = blockIdx.x, tid = ty*32 + tx;
        int p = 0;
        for (int i = tid; i < Nn; i += 256) p += mask[b*Nn + i];
        red[tid] = p; __syncthreads();
        for (int s = 128; s > 0; s >>= 1) { if (tid < s) red[tid] += red[tid+s]; __syncthreads(); }
        if (tid == 0) g_len[b] = red[0];
        return;
    }
    int kx = blockIdx.x * 32, ny = blockIdx.y * 32;
    #pragma unroll
    for (int i = 0; i < 32; i += 8)
        tile[ty + i][tx] = W1[WXY_OFF + (size_t)(kx + ty + i)*768 + ny + tx];
    __syncthreads();
    #pragma unroll
    for (int i = 0; i < 32; i += 8)
        g_W8[(size_t)(ny + ty + i)*768 + kx + tx] =
            __nv_cvt_float_to_fp8(tile[tx][ty + i] * 64.0f, __NV_SATFINITE, __NV_E4M3);
}

// ======= approx main GEMM: persistent-A e4m3 k32, M=64, warp-private B, unrolled =======
__global__ void __launch_bounds__(256, 2)
mma_main(const float* __restrict__ emb, const int* __restrict__ spans,
         const float* __restrict__ ws, const float* __restrict__ b_s) {
    extern __shared__ char sm[];
    const uint32_t sb0 = smem_u32(sm);
    int*   sXo = (int*)(sm + XO_OFF);
    int*   sYo = (int*)(sm + YO_OFF);
    int*   sRo = (int*)(sm + RO_OFF);
    float* red = (float*)(sm + RED_OFF);   // aliases B (post-loop only)

    const int tid = threadIdx.x, wid = tid >> 5, lane = tid & 31;
    const int m0 = blockIdx.x * 64;
    const int g = lane >> 2, t = lane & 3;
    const int warpN = wid;            // 8 warps x 16 n

    if (tid < 64) {
        int m = m0 + tid;
        int sid = -1, b = 0;
        if (m < Bz*Ss) { b = m / Ss; sid = m - b*Ss; }
        if (sid >= 0) {
            int s = spans[2*sid], e = spans[2*sid + 1];
            sXo[tid] = (b*Nn + s)*Hh;
            sYo[tid] = (b*Nn + e)*Hh;
            sRo[tid] = (e - s)*Hh;
        } else { sXo[tid] = -1; sYo[tid] = 0; sRo[tid] = 0; }
    }
    __syncthreads();

    // ---- A fill: ONCE per CTA, 64 x 768 e4m3(x*y*8); 4 threads per row ----
    {
        const int lr = tid >> 2;
        const int lk = (tid & 3) * 8;
        const int xoF = sXo[lr];
        const bool fvalid = xoF >= 0;
        const float* xp = emb + (fvalid ? xoF : 0);
        const float* yp = emb + (fvalid ? sYo[lr] : 0);
        char* arow = sm + lr*SAFB;
        #pragma unroll 4
        for (int c = 0; c < 24; c++) {
            const float* xs = xp + c*32 + lk;
            const float* ys = yp + c*32 + lk;
            float4 xa0 = *(const float4*)(xs);
            float4 xa1 = *(const float4*)(xs + 4);
            float4 ya0 = *(const float4*)(ys);
            float4 ya1 = *(const float4*)(ys + 4);
            float v[8] = {xa0.x*ya0.x, xa0.y*ya0.y, xa0.z*ya0.z, xa0.w*ya0.w,
                          xa1.x*ya1.x, xa1.y*ya1.y, xa1.z*ya1.z, xa1.w*ya1.w};
            unsigned short us[4];
            #pragma unroll
            for (int q = 0; q < 4; q++) {
                float2 f2 = fvalid ? make_float2(v[2*q]*ASCALE, v[2*q+1]*ASCALE)
                                   : make_float2(0.f, 0.f);
                us[q] = __nv_cvt_float2_to_fp8x2(f2, __NV_SATFINITE, __NV_E4M3);
            }
            uint2 u;
            u.x = (unsigned)us[0] | ((unsigned)us[1] << 16);
            u.y = (unsigned)us[2] | ((unsigned)us[3] << 16);
            *(uint2*)(arow + c*32 + lk) = u;
        }
    }
    __syncthreads();

    // ldsm lane addressing (hoisted bases)
    const int arow_l = lane & 15;
    const int acolB  = (lane >> 4) << 4;
    uint32_t aBase[4];
    #pragma unroll
    for (int mt = 0; mt < 4; mt++)
        aBase[mt] = sb0 + (mt*16 + arow_l)*SAFB + acolB;
    // B via single ldsm4: lanes 0-15 -> 16 rows (both nt tiles), lanes 16-31 -> +16B
    const uint32_t bBase4 = sb0 + B_OFF + (warpN*16 + (lane & 15))*SBB + ((lane >> 4) << 4);

    // per-warp B fill roles
    const int frow  = lane & 15;
    const int fhalf = (lane >> 4) * 32;
    const uint32_t fillDst = sb0 + B_OFF + (warpN*16 + frow)*SBB + fhalf;

    float pacc[4][2];
    #pragma unroll
    for (int i = 0; i < 4; i++) { pacc[i][0] = 0.f; pacc[i][1] = 0.f; }

    #pragma unroll 1
    for (int nblk = 0; nblk < NBLK; nblk++) {
        const int n0 = nblk * 128;
        const char* src0 = (const char*)g_W8 + (size_t)(n0 + warpN*16 + frow)*768 + fhalf;

        float acc[4][2][4];
        #pragma unroll
        for (int i = 0; i < 4; i++)
            #pragma unroll
            for (int j = 0; j < 2; j++)
                #pragma unroll
                for (int q = 0; q < 4; q++) acc[i][j][q] = 0.f;

        // per-warp prologue: chunks 0,1 in flight
        cp_async16(fillDst,      src0);
        cp_async16(fillDst + 16, src0 + 16);
        CP_COMMIT();
        cp_async16(fillDst + BSTG_BYTES,      src0 + 64);
        cp_async16(fillDst + BSTG_BYTES + 16, src0 + 80);
        CP_COMMIT();
        CP_WAIT1();
        __syncwarp();

        #pragma unroll
        for (int cc = 0; cc < 12; cc++) {
            const int p = cc % NSTG;
            if (cc + 2 < 12) {
                const int pn = (cc + 2) % NSTG;
                const char* src = src0 + (cc + 2)*64;
                cp_async16(fillDst + pn*BSTG_BYTES,      src);
                cp_async16(fillDst + pn*BSTG_BYTES + 16, src + 16);
                CP_COMMIT();
            }
            const uint32_t pOff = (uint32_t)(p*BSTG_BYTES);
            const uint32_t aOff = (uint32_t)(cc*64);
            #pragma unroll
            for (int s = 0; s < 2; s++) {
                const int koB = s*32;
                unsigned af[4][4], bq[4];
                #pragma unroll
                for (int mt = 0; mt < 4; mt++)
                    ldsm4(af[mt], aBase[mt] + aOff + koB);
                ldsm4(bq, bBase4 + pOff + koB);
                unsigned bf0[2] = {bq[0], bq[2]};
                unsigned bf1[2] = {bq[1], bq[3]};
                #pragma unroll
                for (int mt = 0; mt < 4; mt++) {
                    mma16832(acc[mt][0], af[mt], bf0);
                    mma16832(acc[mt][1], af[mt], bf1);
                }
            }
            if (cc + 2 < 12)     CP_WAIT1();
            else                 CP_WAIT0();
            __syncwarp();
        }

        // per-nblk epilogue (warp-local): accumulate h . ws
        float wv[2][2];
        #pragma unroll
        for (int nt = 0; nt < 2; nt++) {
            float2 Wv = *(const float2*)&ws[n0 + warpN*16 + nt*8 + 2*t];
            wv[nt][0] = Wv.x; wv[nt][1] = Wv.y;
        }
        #pragma unroll
        for (int mt = 0; mt < 4; mt++) {
            #pragma unroll
            for (int rr = 0; rr < 2; rr++) {
                int ml = mt*16 + g + rr*8;
                int xo2 = sXo[ml];
                if (xo2 >= 0) {
                    int yo2 = sYo[ml], ro2 = sRo[ml];
                    float p = 0.f;
                    #pragma unroll
                    for (int nt = 0; nt < 2; nt++) {
                        int n = n0 + warpN*16 + nt*8 + 2*t;
                        float2 Pv = *(const float2*)&g_P[xo2 + n];
                        float2 Qv = *(const float2*)&g_Q[yo2 + n];
                        float2 Rv = *(const float2*)&g_R[ro2 + n];
                        float h0 = gelu_fast(acc[mt][nt][rr*2]*INVSCALE   + Pv.x + Qv.x + Rv.x);
                        float h1 = gelu_fast(acc[mt][nt][rr*2+1]*INVSCALE + Pv.y + Qv.y + Rv.y);
                        p += h0*wv[nt][0] + h1*wv[nt][1];
                    }
                    pacc[mt][rr] += p;
                }
            }
        }
    }

    // all warps done with B region -> safe to alias red
    __syncthreads();
    #pragma unroll
    for (int mt = 0; mt < 4; mt++) {
        #pragma unroll
        for (int rr = 0; rr < 2; rr++) {
            float p = pacc[mt][rr];
            p += __shfl_xor_sync(0xffffffffu, p, 1);
            p += __shfl_xor_sync(0xffffffffu, p, 2);
            if (t == 0) {
                int ml = mt*16 + g + rr*8;
                red[ml*8 + warpN] = p;
            }
        }
    }
    __syncthreads();
    if (tid < 64) {
        int m = m0 + tid;
        if (m < Bz*Ss && sXo[tid] >= 0) {
            int b = m / Ss, sid = m - b*Ss;
            float sc = b_s[0];
            #pragma unroll
            for (int q = 0; q < 8; q++) sc += red[tid*8 + q];
            int e = spans[2*sid + 1];
            if (e >= g_len[b]) sc += -1000000.0f;
            g_scores[m] = sc;
            unsigned u = __float_as_uint(sc);
            g_keys[m] = (u & 0x80000000u) ? ~u : (u | 0x80000000u);
        }
    }
}

// ================= exact P/Q GEMM, 64x128 tiles (fp32x2), 384 CTAs =================
__global__ void __launch_bounds__(256)
pq_kernel(const float* __restrict__ emb, const float* __restrict__ W1) {
    __shared__ float As[2][8][64];
    __shared__ float Bs[2][8][128];
    const int tid = threadIdx.x;
    const int n0 = blockIdx.x * 128;
    const int m0 = blockIdx.y * 64;
    const float* W = W1 + (size_t)blockIdx.z * WBLK;
    float* C = blockIdx.z ? g_Q : g_P;

    const int tx = tid & 15, ty = tid >> 4;
    const int ar = tid >> 2, ac = (tid & 3) * 2;
    const int br = tid >> 5, bc = (tid & 31) * 4;
    const size_t Xo = (size_t)(m0 + ar)*Hh;

    unsigned long long acc[4][4];
    #pragma unroll
    for (int i = 0; i < 4; i++)
        #pragma unroll
        for (int j = 0; j < 4; j++) acc[i][j] = 0ULL;

    float2 xv = *(const float2*)(emb + Xo + ac);
    float4 bv = *(const float4*)(W + (size_t)br*Hh + n0 + bc);
    As[0][ac+0][ar] = xv.x; As[0][ac+1][ar] = xv.y;
    *(float4*)&Bs[0][br][bc] = bv;
    __syncthreads();

    for (int k0 = 0; k0 < Hh; k0 += 8) {
        const int p = (k0 >> 3) & 1;
        const bool more = (k0 + 8) < Hh;
        float2 nxv; float4 nbv;
        if (more) {
            nxv = *(const float2*)(emb + Xo + k0 + 8 + ac);
            nbv = *(const float4*)(W + (size_t)(k0 + 8 + br)*Hh + n0 + bc);
        }
        #pragma unroll
        for (int kk = 0; kk < 8; kk++) {
            float4 a4 = *(float4*)&As[p][kk][ty*4];
            ulonglong2 b01 = *(ulonglong2*)&Bs[p][kk][tx*8];
            ulonglong2 b23 = *(ulonglong2*)&Bs[p][kk][tx*8 + 4];
            float aa[4] = {a4.x, a4.y, a4.z, a4.w};
            unsigned long long bp[4] = {b01.x, b01.y, b23.x, b23.y};
            #pragma unroll
            for (int i = 0; i < 4; i++) {
                unsigned long long ad;
                asm("mov.b64 %0, {%1,%1};" : "=l"(ad) : "f"(aa[i]));
                #pragma unroll
                for (int j = 0; j < 4; j++)
                    asm("fma.rn.f32x2 %0, %1, %2, %0;" : "+l"(acc[i][j]) : "l"(ad), "l"(bp[j]));
            }
        }
        if (more) {
            As[p^1][ac+0][ar] = nxv.x; As[p^1][ac+1][ar] = nxv.y;
            *(float4*)&Bs[p^1][br][bc] = nbv;
        }
        __syncthreads();
    }

    #pragma unroll
    for (int i = 0; i < 4; i++) {
        int m = m0 + ty*4 + i;
        float o[8];
        #pragma unroll
        for (int j = 0; j < 4; j++) {
            float lo, hi;
            asm("mov.b64 {%0,%1}, %2;" : "=f"(lo), "=f"(hi) : "l"(acc[i][j]));
            o[2*j] = lo; o[2*j+1] = hi;
        }
        int col0 = n0 + tx*8;
        *(float4*)&C[(size_t)m*Hh + col0]     = make_float4(o[0],o[1],o[2],o[3]);
        *(float4*)&C[(size_t)m*Hh + col0 + 4] = make_float4(o[4],o[5],o[6],o[7]);
    }
}

// ===== exact rescore GEMM: 64x128 tiles, rows = candidates; h -> g_Hc, partials -> g_part2 =====
__global__ void __launch_bounds__(256)
rescore_gemm(const float* __restrict__ emb, const int* __restrict__ spans,
             const float* __restrict__ W, const float* __restrict__ ws) {
    __shared__ float As[2][8][64];
    __shared__ float Bs[2][8][128];
    __shared__ int sXo[64], sYo[64], sRo[64];
    __shared__ float red[64][17];

    const int tid = threadIdx.x;
    const int n0 = blockIdx.x * 128;
    const int m0 = blockIdx.y * 64;

    if (tid < 64) {
        int m = m0 + tid;
        int sid = -1, b = m >> 10;
        int j = m & (CAP - 1);
        if (b < Bz && j < g_nc[b]) sid = g_cand[m] - b*Ss;
        if (sid >= 0) {
            int s = spans[2*sid], e = spans[2*sid + 1];
            sXo[tid] = (b*Nn + s)*Hh;
            sYo[tid] = (b*Nn + e)*Hh;
            sRo[tid] = (e - s)*Hh;
        } else { sXo[tid] = -1; sYo[tid] = 0; sRo[tid] = 0; }
    }
    __syncthreads();

    const int tx = tid & 15, ty = tid >> 4;
    const int ar = tid >> 2, ac = (tid & 3) * 2;
    const int br = tid >> 5, bc = (tid & 31) * 4;

    const int xoRaw = sXo[ar];
    const int Xo = (xoRaw < 0) ? 0 : xoRaw;
    const int Yo = (xoRaw < 0) ? 0 : sYo[ar];

    unsigned long long acc[4][4];
    #pragma unroll
    for (int i = 0; i < 4; i++)
        #pragma unroll
        for (int j = 0; j < 4; j++) acc[i][j] = 0ULL;

    float2 xv = *(const float2*)(emb + Xo + ac);
    float2 yv = *(const float2*)(emb + Yo + ac);
    xv.x *= yv.x; xv.y *= yv.y;
    float4 bv = *(const float4*)(W + (size_t)br*Hh + n0 + bc);
    As[0][ac+0][ar] = xv.x; As[0][ac+1][ar] = xv.y;
    *(float4*)&Bs[0][br][bc] = bv;
    __syncthreads();

    for (int k0 = 0; k0 < Hh; k0 += 8) {
        const int p = (k0 >> 3) & 1;
        const bool more = (k0 + 8) < Hh;
        float2 nxv; float4 nbv;
        if (more) {
            nxv = *(const float2*)(emb + Xo + k0 + 8 + ac);
            float2 yv2 = *(const float2*)(emb + Yo + k0 + 8 + ac);
            nxv.x *= yv2.x; nxv.y *= yv2.y;
            nbv = *(const float4*)(W + (size_t)(k0 + 8 + br)*Hh + n0 + bc);
        }
        #pragma unroll
        for (int kk = 0; kk < 8; kk++) {
            float4 a4 = *(float4*)&As[p][kk][ty*4];
            ulonglong2 b01 = *(ulonglong2*)&Bs[p][kk][tx*8];
            ulonglong2 b23 = *(ulonglong2*)&Bs[p][kk][tx*8 + 4];
            float aa[4] = {a4.x, a4.y, a4.z, a4.w};
            unsigned long long bp[4] = {b01.x, b01.y, b23.x, b23.y};
            #pragma unroll
            for (int i = 0; i < 4; i++) {
                unsigned long long ad;
                asm("mov.b64 %0, {%1,%1};" : "=l"(ad) : "f"(aa[i]));
                #pragma unroll
                for (int j = 0; j < 4; j++)
                    asm("fma.rn.f32x2 %0, %1, %2, %0;" : "+l"(acc[i][j]) : "l"(ad), "l"(bp[j]));
            }
        }
        if (more) {
            As[p^1][ac+0][ar] = nxv.x; As[p^1][ac+1][ar] = nxv.y;
            *(float4*)&Bs[p^1][br][bc] = nbv;
        }
        __syncthreads();
    }

    #pragma unroll
    for (int i = 0; i < 4; i++) {
        int r = ty*4 + i;
        int xo = sXo[r];
        int m = m0 + r;
        float o[8];
        #pragma unroll
        for (int j = 0; j < 4; j++) {
            float lo, hi;
            asm("mov.b64 {%0,%1}, %2;" : "=f"(lo), "=f"(hi) : "l"(acc[i][j]));
            o[2*j] = lo; o[2*j+1] = hi;
        }
        int col0 = n0 + tx*8;
        float partial = 0.f;
        if (xo >= 0) {
            int yo = sYo[r], ro = sRo[r];
            #pragma unroll
            for (int j = 0; j < 8; j++) {
                int c = col0 + j;
                float pre = o[j] + g_P[xo + c] + g_Q[yo + c] + g_R[ro + c];
                o[j] = gelu_exact(pre);
                partial += o[j] * ws[c];
            }
            *(float4*)&g_Hc[(size_t)m*Hh + col0]     = make_float4(o[0],o[1],o[2],o[3]);
            *(float4*)&g_Hc[(size_t)m*Hh + col0 + 4] = make_float4(o[4],o[5],o[6],o[7]);
        }
        red[r][tx] = partial;
    }
    __syncthreads();
    if (tid < 64) {
        float s = 0.f;
        #pragma unroll
        for (int j = 0; j < 16; j++) s += red[tid][j];
        if (sXo[tid] >= 0)
            g_part2[blockIdx.x*(2*CAP) + m0 + tid] = s;
    }
}

// ---------------- kth-largest key (approx, rank KEXT), 4-pass radix ----------------
__global__ void radix_kernel(int k) {
    __shared__ int hist[256];
    __shared__ unsigned s_prefix, s_mask;
    __shared__ int s_kneed;
    int b = blockIdx.x, tid = threadIdx.x;
    if (tid == 0) { s_prefix = 0u; s_mask = 0u; s_kneed = k; }
    __syncthreads();
    for (int shift = 24; shift >= 0; shift -= 8) {
        for (int i = tid; i < 256; i += blockDim.x) hist[i] = 0;
        __syncthreads();
        unsigned pm = s_mask, pf = s_prefix;
        for (int i = tid; i < Ss; i += blockDim.x) {
            unsigned key = g_keys[b*Ss + i];
            if ((key & pm) == pf) atomicAdd(&hist[(key >> shift) & 255], 1);
        }
        __syncthreads();
        if (tid == 0) {
            int cum = 0, kn = s_kneed;
            for (int bin = 255; bin >= 0; bin--) {
                int h = hist[bin];
                if (kn <= cum + h) {
                    s_prefix = pf | ((unsigned)bin << shift);
                    s_kneed = kn - cum;
                    s_mask  = pm | (0xFFu << shift);
                    break;
                }
                cum += h;
            }
        }
        __syncthreads();
    }
    if (tid == 0) g_thr[b] = s_prefix;
}

// ---------------- candidate filter ----------------
__global__ void filter_kernel() {
    __shared__ int cnt;
    int b = blockIdx.x, tid = threadIdx.x;
    if (tid == 0) cnt = 0;
    __syncthreads();
    unsigned T = g_thr[b];
    for (int i = tid; i < Ss; i += 1024) {
        if (g_keys[b*Ss + i] >= T) {
            int p = atomicAdd(&cnt, 1);
            if (p < CAP) g_cand[b*CAP + p] = b*Ss + i;
        }
    }
    __syncthreads();
    if (tid == 0) g_nc[b] = (cnt < CAP) ? cnt : CAP;
}

// ---------------- exact rescore assemble ----------------
__global__ void rescore_reduce(const int* __restrict__ spans,
                               const float* __restrict__ b_s) {
    int t = blockIdx.x * 256 + threadIdx.x;
    if (t >= Bz*CAP) return;
    int b = t >> 10, j = t & (CAP - 1);
    if (j >= g_nc[b]) return;
    int i = g_cand[t];
    float sc = b_s[0];
    #pragma unroll
    for (int nb = 0; nb < NBLK; nb++) sc += g_part2[nb*(2*CAP) + t];
    int sid = i - b*Ss;
    int e = spans[2*sid + 1];
    if (e >= g_len[b]) sc += -1000000.0f;
    g_scores[i] = sc;
    unsigned u = __float_as_uint(sc);
    g_keys[i] = (u & 0x80000000u) ? ~u : (u | 0x80000000u);
}

// ---------------- final exact selection (per batch); carries candidate slot ----------------
__global__ void final_select_kernel() {
    __shared__ unsigned long long comp[CAP];
    __shared__ int sel2[512];
    int b = blockIdx.x, tid = threadIdx.x;
    int nc = g_nc[b];
    if (tid < nc) {
        int i = g_cand[b*CAP + tid];
        unsigned key = g_keys[i];
        unsigned sid = (unsigned)(i - b*Ss);
        comp[tid] = ((unsigned long long)(~key) << 32) | ((unsigned long long)sid << 10)
                    | (unsigned long long)tid;
    } else {
        comp[tid] = 0xFFFFFFFFFFFFFFFFull;
    }
    __syncthreads();
    for (int sz = 2; sz <= CAP; sz <<= 1) {
        for (int j = sz >> 1; j > 0; j >>= 1) {
            int ix = tid ^ j;
            if (ix > tid) {
                bool up = ((tid & sz) == 0);
                unsigned long long a = comp[tid], c = comp[ix];
                if ((a > c) == up) { comp[tid] = c; comp[ix] = a; }
            }
            __syncthreads();
        }
    }
    if (tid < 512)
        sel2[tid] = (tid < Kk) ? (int)(unsigned)(comp[tid] & 0x1FFFFFFull) : 0x7FFFFFFF;
    __syncthreads();
    for (int sz = 2; sz <= 512; sz <<= 1) {
        for (int j = sz >> 1; j > 0; j >>= 1) {
            if (tid < 512) {
                int ix = tid ^ j;
                if (ix > tid) {
                    bool up = ((tid & sz) == 0);
                    int a = sel2[tid], c = sel2[ix];
                    if ((a > c) == up) { sel2[tid] = c; sel2[ix] = a; }
                }
            }
            __syncthreads();
        }
    }
    if (tid < Kk) {
        g_sel[b*Kk + tid]  = sel2[tid] >> 10;
        g_slot[b*Kk + tid] = sel2[tid] & 1023;
    }
}

// ---------------- gather: cached h rows + scores + spans -> out ----------------
__global__ void gather_kernel(const int* __restrict__ spans, float* __restrict__ out) {
    int j = blockIdx.x, b = blockIdx.y, tid = threadIdx.x;
    int t = b*Kk + j;
    int sid = g_sel[t], slot = g_slot[t];
    const float* src = g_Hc + (size_t)(b*CAP + slot)*Hh;
    float* dst = out + (size_t)t*Hh;
    for (int c = tid; c < Hh; c += blockDim.x) dst[c] = src[c];
    if (tid == 0) {
        size_t sc_base = (size_t)Bz*Kk*Hh;
        out[sc_base + t] = g_scores[b*Ss + sid];
        size_t sp_base = sc_base + (size_t)Bz*Kk;
        out[sp_base + (size_t)t*2]     = (float)spans[2*sid];
        out[sp_base + (size_t)t*2 + 1] = (float)spans[2*sid + 1];
    }
}

__global__ void fill_tail_kernel(float* out, long long begin, long long end) {
    long long i = begin + blockIdx.x * (long long)blockDim.x + threadIdx.x;
    if (i < end) out[i] = 0.0f;
}

extern "C" void kernel_launch(void* const* d_in, const int* in_sizes, int n_in,
                              void* d_out, int out_size) {
    const float* emb   = (const float*)d_in[0];
    const int*   mask  = (const int*)  d_in[1];
    const int*   spans = (const int*)  d_in[2];
    const float* wemb  = (const float*)d_in[3];
    const float* W1    = (const float*)d_in[4];
    const float* b1    = (const float*)d_in[5];
    const float* w_s   = (const float*)d_in[6];
    const float* b_s   = (const float*)d_in[7];
    float* out = (float*)d_out;
    (void)n_in; (void)in_sizes;

    cudaFuncSetAttribute(mma_main, cudaFuncAttributeMaxDynamicSharedMemorySize, DYNSMEM);

    // launch 1: R (+b1)
    r_kernel<<<MAXW, 256>>>(wemb, W1, b1);
    // launch 2: weight transpose -> fp8 (+ fused mask lengths)
    prep2_kernel<<<dim3(24, 25), dim3(32, 8)>>>(W1, mask);
    // launch 3: exact P and Q (64x128 tiles, 384 CTAs)
    pq_kernel<<<dim3(NBLK, (Bz*Nn)/64, 2), 256>>>(emb, W1);
    // launch 4 (ncu-captured): approx main GEMM, unrolled warp-private pipeline
    mma_main<<<MTILES64, 256, DYNSMEM>>>(emb, spans, w_s, b_s);

    radix_kernel<<<Bz, 1024>>>(KEXT);
    filter_kernel<<<Bz, 1024>>>();

    // exact rescore (64x128 tiles, 192 CTAs)
    rescore_gemm<<<dim3(NBLK, (Bz*CAP)/64), 256>>>(emb, spans, W1 + WXY_OFF, w_s);
    rescore_reduce<<<(Bz*CAP + 255)/256, 256>>>(spans, b_s);

    final_select_kernel<<<Bz, CAP>>>();
    gather_kernel<<<dim3(Kk, Bz), 192>>>(spans, out);

    long long written = (long long)Bz*Kk*Hh + (long long)Bz*Kk + (long long)Bz*Kk*2;
    if ((long long)out_size > written) {
        long long extra = (long long)out_size - written;
        int blocks = (int)((extra + 255) / 256);
        fill_tail_kernel<<<blocks, 256>>>(out, written, (long long)out_size);
    }
}

// round 16
// speedup vs baseline: 1.1334x; 1.1334x over previous
#include <cuda_runtime.h>
#include <cuda_bf16.h>
#include <cuda_fp8.h>
#include <math.h>
#include <stdint.h>

#define Bz   2
#define Nn   1024
#define Hh   768
#define Ss   30285
#define Kk   409
#define MAXW 30
#define WD   20
#define NBLK 6
#define MTILES64 947              // ceil(Bz*Ss/64)
#define CAP  1024
#define KEXT (Kk + 512)
#define WXY_OFF (1536*768)
#define WW_ROW 2304
#define WBLK (768*768)

// ---- mma_main smem layout (bytes), fp8, M=64 ----
#define SAFB  784                 // A row stride bytes
#define A_BYTES (64*SAFB)         // 50176
#define SBB   80                  // B row stride bytes
#define BSTG_BYTES (128*SBB)      // 10240 per stage
#define NSTG  3
#define B_OFF A_BYTES
#define RED_OFF B_OFF             // red aliases B region (post-loop only)
#define XO_OFF (A_BYTES + NSTG*BSTG_BYTES)   // 80896
#define YO_OFF (XO_OFF + 256)
#define RO_OFF (YO_OFF + 256)
#define DYNSMEM (RO_OFF + 256)               // 81664  -> 2 CTAs/SM

#define ASCALE 8.0f
#define INVSCALE (1.0f/512.0f)

__device__ __forceinline__ float gelu_exact(float x) {
    return 0.5f * x * (1.0f + erff(x * 0.70710678118654752f));
}
__device__ __forceinline__ float gelu_fast(float x) {
    float arg = 0.7978845608028654f * (x + 0.044715f * x * x * x);
    float th;
    asm("tanh.approx.f32 %0, %1;" : "=f"(th) : "f"(arg));
    return 0.5f * x * (1.0f + th);
}
__device__ __forceinline__ uint32_t smem_u32(const void* p) {
    uint32_t a;
    asm("{ .reg .u64 t; cvta.to.shared.u64 t, %1; cvt.u32.u64 %0, t; }" : "=r"(a) : "l"(p));
    return a;
}
__device__ __forceinline__ void cp_async16(uint32_t dst, const void* src) {
    asm volatile("cp.async.cg.shared.global [%0], [%1], 16;" :: "r"(dst), "l"(src));
}
#define CP_COMMIT() asm volatile("cp.async.commit_group;" ::: "memory")
#define CP_WAIT0()  asm volatile("cp.async.wait_group 0;" ::: "memory")
#define CP_WAIT1()  asm volatile("cp.async.wait_group 1;" ::: "memory")

__device__ __forceinline__ void mma16832(float* c, const unsigned* a, const unsigned* b) {
    asm volatile("mma.sync.aligned.m16n8k32.row.col.f32.e4m3.e4m3.f32 "
        "{%0,%1,%2,%3}, {%4,%5,%6,%7}, {%8,%9}, {%0,%1,%2,%3};"
        : "+f"(c[0]), "+f"(c[1]), "+f"(c[2]), "+f"(c[3])
        : "r"(a[0]), "r"(a[1]), "r"(a[2]), "r"(a[3]), "r"(b[0]), "r"(b[1]));
}
__device__ __forceinline__ void ldsm4(unsigned* r, uint32_t addr) {
    asm volatile("ldmatrix.sync.aligned.m8n8.x4.shared.b16 {%0,%1,%2,%3}, [%4];"
        : "=r"(r[0]), "=r"(r[1]), "=r"(r[2]), "=r"(r[3]) : "r"(addr));
}

// ---------------- scratch ----------------
__device__ unsigned char g_W8[768*768]; // e4m3(Wxy * 64) transposed [n][k]
__device__ float    g_P[Bz*Nn*Hh];
__device__ float    g_Q[Bz*Nn*Hh];
__device__ float    g_R[MAXW*Hh];
__device__ float    g_part2[NBLK*2*CAP];
__device__ float    g_Hc[(size_t)Bz*CAP*Hh];
__device__ float    g_scores[Bz*Ss];
__device__ unsigned g_keys[Bz*Ss];
__device__ int      g_len[Bz];
__device__ unsigned g_thr[Bz];
__device__ int      g_cand[Bz*CAP];
__device__ int      g_nc[Bz];
__device__ int      g_sel[Bz*Kk];
__device__ int      g_slot[Bz*Kk];

// ---------------- R[w] = width_emb[w] @ Ww + b1 ----------------
__global__ void r_kernel(const float* __restrict__ wemb,
                         const float* __restrict__ W1,
                         const float* __restrict__ b1) {
    int w = blockIdx.x;
    for (int c = threadIdx.x; c < Hh; c += blockDim.x) {
        float a = b1[c];
        #pragma unroll
        for (int j = 0; j < WD; j++) a += wemb[w*WD + j] * W1[(WW_ROW + j)*Hh + c];
        g_R[w*Hh + c] = a;
    }
}

// ---------------- Wxy -> transposed e4m3 (x64) + (fused) lengths ----------------
__global__ void prep2_kernel(const float* __restrict__ W1, const int* __restrict__ mask) {
    __shared__ float tile[32][33];
    int tx = threadIdx.x, ty = threadIdx.y;   // 32 x 8
    if (blockIdx.y == 24) {
        if (blockIdx.x >= Bz) return;
        __shared__ int red[256];
        int b = blockIdx.x, tid = ty*32 + tx;
        int p = 0;
        for (int i = tid; i < Nn; i += 256) p += mask[b*Nn + i];
        red[tid] = p; __syncthreads();
        for (int s = 128; s > 0; s >>= 1) { if (tid < s) red[tid] += red[tid+s]; __syncthreads(); }
        if (tid == 0) g_len[b] = red[0];
        return;
    }
    int kx = blockIdx.x * 32, ny = blockIdx.y * 32;
    #pragma unroll
    for (int i = 0; i < 32; i += 8)
        tile[ty + i][tx] = W1[WXY_OFF + (size_t)(kx + ty + i)*768 + ny + tx];
    __syncthreads();
    #pragma unroll
    for (int i = 0; i < 32; i += 8)
        g_W8[(size_t)(ny + ty + i)*768 + kx + tx] =
            __nv_cvt_float_to_fp8(tile[tx][ty + i] * 64.0f, __NV_SATFINITE, __NV_E4M3);
}

// ======= approx main GEMM: persistent-A e4m3 k32, M=64, warp-private B, unrolled =======
__global__ void __launch_bounds__(256, 2)
mma_main(const float* __restrict__ emb, const int* __restrict__ spans,
         const float* __restrict__ ws, const float* __restrict__ b_s) {
    extern __shared__ char sm[];
    const uint32_t sb0 = smem_u32(sm);
    int*   sXo = (int*)(sm + XO_OFF);
    int*   sYo = (int*)(sm + YO_OFF);
    int*   sRo = (int*)(sm + RO_OFF);
    float* red = (float*)(sm + RED_OFF);   // aliases B (post-loop only)

    const int tid = threadIdx.x, wid = tid >> 5, lane = tid & 31;
    const int m0 = blockIdx.x * 64;
    const int g = lane >> 2, t = lane & 3;
    const int warpN = wid;            // 8 warps x 16 n

    if (tid < 64) {
        int m = m0 + tid;
        int sid = -1, b = 0;
        if (m < Bz*Ss) { b = m / Ss; sid = m - b*Ss; }
        if (sid >= 0) {
            int s = spans[2*sid], e = spans[2*sid + 1];
            sXo[tid] = (b*Nn + s)*Hh;
            sYo[tid] = (b*Nn + e)*Hh;
            sRo[tid] = (e - s)*Hh;
        } else { sXo[tid] = -1; sYo[tid] = 0; sRo[tid] = 0; }
    }
    __syncthreads();

    // ---- A fill: ONCE per CTA, 64 x 768 e4m3(x*y*8); 4 threads per row ----
    {
        const int lr = tid >> 2;
        const int lk = (tid & 3) * 8;
        const int xoF = sXo[lr];
        const bool fvalid = xoF >= 0;
        const float* xp = emb + (fvalid ? xoF : 0);
        const float* yp = emb + (fvalid ? sYo[lr] : 0);
        char* arow = sm + lr*SAFB;
        #pragma unroll 4
        for (int c = 0; c < 24; c++) {
            const float* xs = xp + c*32 + lk;
            const float* ys = yp + c*32 + lk;
            float4 xa0 = *(const float4*)(xs);
            float4 xa1 = *(const float4*)(xs + 4);
            float4 ya0 = *(const float4*)(ys);
            float4 ya1 = *(const float4*)(ys + 4);
            float v[8] = {xa0.x*ya0.x, xa0.y*ya0.y, xa0.z*ya0.z, xa0.w*ya0.w,
                          xa1.x*ya1.x, xa1.y*ya1.y, xa1.z*ya1.z, xa1.w*ya1.w};
            unsigned short us[4];
            #pragma unroll
            for (int q = 0; q < 4; q++) {
                float2 f2 = fvalid ? make_float2(v[2*q]*ASCALE, v[2*q+1]*ASCALE)
                                   : make_float2(0.f, 0.f);
                us[q] = __nv_cvt_float2_to_fp8x2(f2, __NV_SATFINITE, __NV_E4M3);
            }
            uint2 u;
            u.x = (unsigned)us[0] | ((unsigned)us[1] << 16);
            u.y = (unsigned)us[2] | ((unsigned)us[3] << 16);
            *(uint2*)(arow + c*32 + lk) = u;
        }
    }
    __syncthreads();

    // ldsm lane addressing (hoisted bases)
    const int arow_l = lane & 15;
    const int acolB  = (lane >> 4) << 4;
    uint32_t aBase[4];
    #pragma unroll
    for (int mt = 0; mt < 4; mt++)
        aBase[mt] = sb0 + (mt*16 + arow_l)*SAFB + acolB;
    const uint32_t bBase4 = sb0 + B_OFF + (warpN*16 + (lane & 15))*SBB + ((lane >> 4) << 4);

    // per-warp B fill roles
    const int frow  = lane & 15;
    const int fhalf = (lane >> 4) * 32;
    const uint32_t fillDst = sb0 + B_OFF + (warpN*16 + frow)*SBB + fhalf;

    float pacc[4][2];
    #pragma unroll
    for (int i = 0; i < 4; i++) { pacc[i][0] = 0.f; pacc[i][1] = 0.f; }

    #pragma unroll 1
    for (int nblk = 0; nblk < NBLK; nblk++) {
        const int n0 = nblk * 128;
        const char* src0 = (const char*)g_W8 + (size_t)(n0 + warpN*16 + frow)*768 + fhalf;

        float acc[4][2][4];
        #pragma unroll
        for (int i = 0; i < 4; i++)
            #pragma unroll
            for (int j = 0; j < 2; j++)
                #pragma unroll
                for (int q = 0; q < 4; q++) acc[i][j][q] = 0.f;

        // per-warp prologue: chunks 0,1 in flight
        cp_async16(fillDst,      src0);
        cp_async16(fillDst + 16, src0 + 16);
        CP_COMMIT();
        cp_async16(fillDst + BSTG_BYTES,      src0 + 64);
        cp_async16(fillDst + BSTG_BYTES + 16, src0 + 80);
        CP_COMMIT();
        CP_WAIT1();
        __syncwarp();

        #pragma unroll
        for (int cc = 0; cc < 12; cc++) {
            const int p = cc % NSTG;
            if (cc + 2 < 12) {
                const int pn = (cc + 2) % NSTG;
                const char* src = src0 + (cc + 2)*64;
                cp_async16(fillDst + pn*BSTG_BYTES,      src);
                cp_async16(fillDst + pn*BSTG_BYTES + 16, src + 16);
                CP_COMMIT();
            }
            const uint32_t pOff = (uint32_t)(p*BSTG_BYTES);
            const uint32_t aOff = (uint32_t)(cc*64);
            #pragma unroll
            for (int s = 0; s < 2; s++) {
                const int koB = s*32;
                unsigned af[4][4], bq[4];
                #pragma unroll
                for (int mt = 0; mt < 4; mt++)
                    ldsm4(af[mt], aBase[mt] + aOff + koB);
                ldsm4(bq, bBase4 + pOff + koB);
                unsigned bf0[2] = {bq[0], bq[2]};
                unsigned bf1[2] = {bq[1], bq[3]};
                #pragma unroll
                for (int mt = 0; mt < 4; mt++) {
                    mma16832(acc[mt][0], af[mt], bf0);
                    mma16832(acc[mt][1], af[mt], bf1);
                }
            }
            if (cc + 2 < 12)     CP_WAIT1();
            else                 CP_WAIT0();
            __syncwarp();
        }

        // per-nblk epilogue (warp-local): accumulate h . ws
        float wv[2][2];
        #pragma unroll
        for (int nt = 0; nt < 2; nt++) {
            float2 Wv = *(const float2*)&ws[n0 + warpN*16 + nt*8 + 2*t];
            wv[nt][0] = Wv.x; wv[nt][1] = Wv.y;
        }
        #pragma unroll
        for (int mt = 0; mt < 4; mt++) {
            #pragma unroll
            for (int rr = 0; rr < 2; rr++) {
                int ml = mt*16 + g + rr*8;
                int xo2 = sXo[ml];
                if (xo2 >= 0) {
                    int yo2 = sYo[ml], ro2 = sRo[ml];
                    float p = 0.f;
                    #pragma unroll
                    for (int nt = 0; nt < 2; nt++) {
                        int n = n0 + warpN*16 + nt*8 + 2*t;
                        float2 Pv = *(const float2*)&g_P[xo2 + n];
                        float2 Qv = *(const float2*)&g_Q[yo2 + n];
                        float2 Rv = *(const float2*)&g_R[ro2 + n];
                        float h0 = gelu_fast(acc[mt][nt][rr*2]*INVSCALE   + Pv.x + Qv.x + Rv.x);
                        float h1 = gelu_fast(acc[mt][nt][rr*2+1]*INVSCALE + Pv.y + Qv.y + Rv.y);
                        p += h0*wv[nt][0] + h1*wv[nt][1];
                    }
                    pacc[mt][rr] += p;
                }
            }
        }
    }

    // all warps done with B region -> safe to alias red
    __syncthreads();
    #pragma unroll
    for (int mt = 0; mt < 4; mt++) {
        #pragma unroll
        for (int rr = 0; rr < 2; rr++) {
            float p = pacc[mt][rr];
            p += __shfl_xor_sync(0xffffffffu, p, 1);
            p += __shfl_xor_sync(0xffffffffu, p, 2);
            if (t == 0) {
                int ml = mt*16 + g + rr*8;
                red[ml*8 + warpN] = p;
            }
        }
    }
    __syncthreads();
    if (tid < 64) {
        int m = m0 + tid;
        if (m < Bz*Ss && sXo[tid] >= 0) {
            int b = m / Ss, sid = m - b*Ss;
            float sc = b_s[0];
            #pragma unroll
            for (int q = 0; q < 8; q++) sc += red[tid*8 + q];
            int e = spans[2*sid + 1];
            if (e >= g_len[b]) sc += -1000000.0f;
            g_scores[m] = sc;
            unsigned u = __float_as_uint(sc);
            g_keys[m] = (u & 0x80000000u) ? ~u : (u | 0x80000000u);
        }
    }
}

// ================= exact P/Q GEMM, 128x128 tiles (fp32x2) — proven version =================
__global__ void __launch_bounds__(256)
pq_kernel(const float* __restrict__ emb, const float* __restrict__ W1) {
    __shared__ float As[2][8][128];
    __shared__ float Bs[2][8][128];
    const int tid = threadIdx.x;
    const int n0 = blockIdx.x * 128;
    const int m0 = blockIdx.y * 128;
    const float* W = W1 + (size_t)blockIdx.z * WBLK;
    float* C = blockIdx.z ? g_Q : g_P;

    const int tx = tid & 15, ty = tid >> 4;
    const int ar = tid >> 1, ac = (tid & 1) * 4;
    const int br = tid >> 5, bc = (tid & 31) * 4;
    const size_t Xo = (size_t)(m0 + ar)*Hh;

    unsigned long long acc[8][4];
    #pragma unroll
    for (int i = 0; i < 8; i++)
        #pragma unroll
        for (int j = 0; j < 4; j++) acc[i][j] = 0ULL;

    float4 xv = *(const float4*)(emb + Xo + ac);
    float4 bv = *(const float4*)(W + (size_t)br*Hh + n0 + bc);
    As[0][ac+0][ar] = xv.x; As[0][ac+1][ar] = xv.y;
    As[0][ac+2][ar] = xv.z; As[0][ac+3][ar] = xv.w;
    *(float4*)&Bs[0][br][bc] = bv;
    __syncthreads();

    for (int k0 = 0; k0 < Hh; k0 += 8) {
        const int p = (k0 >> 3) & 1;
        const bool more = (k0 + 8) < Hh;
        float4 nxv, nbv;
        if (more) {
            nxv = *(const float4*)(emb + Xo + k0 + 8 + ac);
            nbv = *(const float4*)(W + (size_t)(k0 + 8 + br)*Hh + n0 + bc);
        }
        #pragma unroll
        for (int kk = 0; kk < 8; kk++) {
            float4 a0 = *(float4*)&As[p][kk][ty*8];
            float4 a1 = *(float4*)&As[p][kk][ty*8 + 4];
            ulonglong2 b01 = *(ulonglong2*)&Bs[p][kk][tx*8];
            ulonglong2 b23 = *(ulonglong2*)&Bs[p][kk][tx*8 + 4];
            float av[8] = {a0.x,a0.y,a0.z,a0.w,a1.x,a1.y,a1.z,a1.w};
            unsigned long long bp[4] = {b01.x, b01.y, b23.x, b23.y};
            #pragma unroll
            for (int i = 0; i < 8; i++) {
                unsigned long long ad;
                asm("mov.b64 %0, {%1,%1};" : "=l"(ad) : "f"(av[i]));
                #pragma unroll
                for (int j = 0; j < 4; j++)
                    asm("fma.rn.f32x2 %0, %1, %2, %0;" : "+l"(acc[i][j]) : "l"(ad), "l"(bp[j]));
            }
        }
        if (more) {
            As[p^1][ac+0][ar] = nxv.x; As[p^1][ac+1][ar] = nxv.y;
            As[p^1][ac+2][ar] = nxv.z; As[p^1][ac+3][ar] = nxv.w;
            *(float4*)&Bs[p^1][br][bc] = nbv;
        }
        __syncthreads();
    }

    #pragma unroll
    for (int i = 0; i < 8; i++) {
        int m = m0 + ty*8 + i;
        float o[8];
        #pragma unroll
        for (int j = 0; j < 4; j++) {
            float lo, hi;
            asm("mov.b64 {%0,%1}, %2;" : "=f"(lo), "=f"(hi) : "l"(acc[i][j]));
            o[2*j] = lo; o[2*j+1] = hi;
        }
        int col0 = n0 + tx*8;
        *(float4*)&C[(size_t)m*Hh + col0]     = make_float4(o[0],o[1],o[2],o[3]);
        *(float4*)&C[(size_t)m*Hh + col0 + 4] = make_float4(o[4],o[5],o[6],o[7]);
    }
}

// ===== exact rescore GEMM, 128x128 tiles — proven version; h -> g_Hc, partials -> g_part2 =====
__global__ void __launch_bounds__(256)
rescore_gemm(const float* __restrict__ emb, const int* __restrict__ spans,
             const float* __restrict__ W, const float* __restrict__ ws) {
    __shared__ float As[2][8][128];
    __shared__ float Bs[2][8][128];
    __shared__ int sXo[128], sYo[128], sRo[128];
    __shared__ float red[128][17];

    const int tid = threadIdx.x;
    const int n0 = blockIdx.x * 128;
    const int m0 = blockIdx.y * 128;

    if (tid < 128) {
        int m = m0 + tid;
        int sid = -1, b = m >> 10;
        int j = m & (CAP - 1);
        if (b < Bz && j < g_nc[b]) sid = g_cand[m] - b*Ss;
        if (sid >= 0) {
            int s = spans[2*sid], e = spans[2*sid + 1];
            sXo[tid] = (b*Nn + s)*Hh;
            sYo[tid] = (b*Nn + e)*Hh;
            sRo[tid] = (e - s)*Hh;
        } else { sXo[tid] = -1; sYo[tid] = 0; sRo[tid] = 0; }
    }
    __syncthreads();

    const int tx = tid & 15, ty = tid >> 4;
    const int ar = tid >> 1, ac = (tid & 1) * 4;
    const int br = tid >> 5, bc = (tid & 31) * 4;

    const int xoRaw = sXo[ar];
    const int Xo = (xoRaw < 0) ? 0 : xoRaw;
    const int Yo = (xoRaw < 0) ? 0 : sYo[ar];

    unsigned long long acc[8][4];
    #pragma unroll
    for (int i = 0; i < 8; i++)
        #pragma unroll
        for (int j = 0; j < 4; j++) acc[i][j] = 0ULL;

    float4 xv = *(const float4*)(emb + Xo + ac);
    float4 yv = *(const float4*)(emb + Yo + ac);
    xv.x *= yv.x; xv.y *= yv.y; xv.z *= yv.z; xv.w *= yv.w;
    float4 bv = *(const float4*)(W + (size_t)br*Hh + n0 + bc);
    As[0][ac+0][ar] = xv.x; As[0][ac+1][ar] = xv.y;
    As[0][ac+2][ar] = xv.z; As[0][ac+3][ar] = xv.w;
    *(float4*)&Bs[0][br][bc] = bv;
    __syncthreads();

    for (int k0 = 0; k0 < Hh; k0 += 8) {
        const int p = (k0 >> 3) & 1;
        const bool more = (k0 + 8) < Hh;
        float4 nxv, nbv;
        if (more) {
            nxv = *(const float4*)(emb + Xo + k0 + 8 + ac);
            float4 yv2 = *(const float4*)(emb + Yo + k0 + 8 + ac);
            nxv.x *= yv2.x; nxv.y *= yv2.y; nxv.z *= yv2.z; nxv.w *= yv2.w;
            nbv = *(const float4*)(W + (size_t)(k0 + 8 + br)*Hh + n0 + bc);
        }
        #pragma unroll
        for (int kk = 0; kk < 8; kk++) {
            float4 a0 = *(float4*)&As[p][kk][ty*8];
            float4 a1 = *(float4*)&As[p][kk][ty*8 + 4];
            ulonglong2 b01 = *(ulonglong2*)&Bs[p][kk][tx*8];
            ulonglong2 b23 = *(ulonglong2*)&Bs[p][kk][tx*8 + 4];
            float av[8] = {a0.x,a0.y,a0.z,a0.w,a1.x,a1.y,a1.z,a1.w};
            unsigned long long bp[4] = {b01.x, b01.y, b23.x, b23.y};
            #pragma unroll
            for (int i = 0; i < 8; i++) {
                unsigned long long ad;
                asm("mov.b64 %0, {%1,%1};" : "=l"(ad) : "f"(av[i]));
                #pragma unroll
                for (int j = 0; j < 4; j++)
                    asm("fma.rn.f32x2 %0, %1, %2, %0;" : "+l"(acc[i][j]) : "l"(ad), "l"(bp[j]));
            }
        }
        if (more) {
            As[p^1][ac+0][ar] = nxv.x; As[p^1][ac+1][ar] = nxv.y;
            As[p^1][ac+2][ar] = nxv.z; As[p^1][ac+3][ar] = nxv.w;
            *(float4*)&Bs[p^1][br][bc] = nbv;
        }
        __syncthreads();
    }

    #pragma unroll
    for (int i = 0; i < 8; i++) {
        int r = ty*8 + i;
        int xo = sXo[r];
        int m = m0 + r;
        float o[8];
        #pragma unroll
        for (int j = 0; j < 4; j++) {
            float lo, hi;
            asm("mov.b64 {%0,%1}, %2;" : "=f"(lo), "=f"(hi) : "l"(acc[i][j]));
            o[2*j] = lo; o[2*j+1] = hi;
        }
        int col0 = n0 + tx*8;
        float partial = 0.f;
        if (xo >= 0) {
            int yo = sYo[r], ro = sRo[r];
            #pragma unroll
            for (int j = 0; j < 8; j++) {
                int c = col0 + j;
                float pre = o[j] + g_P[xo + c] + g_Q[yo + c] + g_R[ro + c];
                o[j] = gelu_exact(pre);
                partial += o[j] * ws[c];
            }
            *(float4*)&g_Hc[(size_t)m*Hh + col0]     = make_float4(o[0],o[1],o[2],o[3]);
            *(float4*)&g_Hc[(size_t)m*Hh + col0 + 4] = make_float4(o[4],o[5],o[6],o[7]);
        }
        red[r][tx] = partial;
    }
    __syncthreads();
    if (tid < 128) {
        float s = 0.f;
        #pragma unroll
        for (int j = 0; j < 16; j++) s += red[tid][j];
        if (sXo[tid] >= 0)
            g_part2[blockIdx.x*(2*CAP) + m0 + tid] = s;
    }
}

// ---------------- kth-largest key (approx, rank KEXT), 4-pass radix ----------------
__global__ void radix_kernel(int k) {
    __shared__ int hist[256];
    __shared__ unsigned s_prefix, s_mask;
    __shared__ int s_kneed;
    int b = blockIdx.x, tid = threadIdx.x;
    if (tid == 0) { s_prefix = 0u; s_mask = 0u; s_kneed = k; }
    __syncthreads();
    for (int shift = 24; shift >= 0; shift -= 8) {
        for (int i = tid; i < 256; i += blockDim.x) hist[i] = 0;
        __syncthreads();
        unsigned pm = s_mask, pf = s_prefix;
        for (int i = tid; i < Ss; i += blockDim.x) {
            unsigned key = g_keys[b*Ss + i];
            if ((key & pm) == pf) atomicAdd(&hist[(key >> shift) & 255], 1);
        }
        __syncthreads();
        if (tid == 0) {
            int cum = 0, kn = s_kneed;
            for (int bin = 255; bin >= 0; bin--) {
                int h = hist[bin];
                if (kn <= cum + h) {
                    s_prefix = pf | ((unsigned)bin << shift);
                    s_kneed = kn - cum;
                    s_mask  = pm | (0xFFu << shift);
                    break;
                }
                cum += h;
            }
        }
        __syncthreads();
    }
    if (tid == 0) g_thr[b] = s_prefix;
}

// ---------------- candidate filter ----------------
__global__ void filter_kernel() {
    __shared__ int cnt;
    int b = blockIdx.x, tid = threadIdx.x;
    if (tid == 0) cnt = 0;
    __syncthreads();
    unsigned T = g_thr[b];
    for (int i = tid; i < Ss; i += 1024) {
        if (g_keys[b*Ss + i] >= T) {
            int p = atomicAdd(&cnt, 1);
            if (p < CAP) g_cand[b*CAP + p] = b*Ss + i;
        }
    }
    __syncthreads();
    if (tid == 0) g_nc[b] = (cnt < CAP) ? cnt : CAP;
}

// ---------------- exact rescore assemble ----------------
__global__ void rescore_reduce(const int* __restrict__ spans,
                               const float* __restrict__ b_s) {
    int t = blockIdx.x * 256 + threadIdx.x;
    if (t >= Bz*CAP) return;
    int b = t >> 10, j = t & (CAP - 1);
    if (j >= g_nc[b]) return;
    int i = g_cand[t];
    float sc = b_s[0];
    #pragma unroll
    for (int nb = 0; nb < NBLK; nb++) sc += g_part2[nb*(2*CAP) + t];
    int sid = i - b*Ss;
    int e = spans[2*sid + 1];
    if (e >= g_len[b]) sc += -1000000.0f;
    g_scores[i] = sc;
    unsigned u = __float_as_uint(sc);
    g_keys[i] = (u & 0x80000000u) ? ~u : (u | 0x80000000u);
}

// ---------------- final exact selection (per batch); carries candidate slot ----------------
__global__ void final_select_kernel() {
    __shared__ unsigned long long comp[CAP];
    __shared__ int sel2[512];
    int b = blockIdx.x, tid = threadIdx.x;
    int nc = g_nc[b];
    if (tid < nc) {
        int i = g_cand[b*CAP + tid];
        unsigned key = g_keys[i];
        unsigned sid = (unsigned)(i - b*Ss);
        comp[tid] = ((unsigned long long)(~key) << 32) | ((unsigned long long)sid << 10)
                    | (unsigned long long)tid;
    } else {
        comp[tid] = 0xFFFFFFFFFFFFFFFFull;
    }
    __syncthreads();
    for (int sz = 2; sz <= CAP; sz <<= 1) {
        for (int j = sz >> 1; j > 0; j >>= 1) {
            int ix = tid ^ j;
            if (ix > tid) {
                bool up = ((tid & sz) == 0);
                unsigned long long a = comp[tid], c = comp[ix];
                if ((a > c) == up) { comp[tid] = c; comp[ix] = a; }
            }
            __syncthreads();
        }
    }
    if (tid < 512)
        sel2[tid] = (tid < Kk) ? (int)(unsigned)(comp[tid] & 0x1FFFFFFull) : 0x7FFFFFFF;
    __syncthreads();
    for (int sz = 2; sz <= 512; sz <<= 1) {
        for (int j = sz >> 1; j > 0; j >>= 1) {
            if (tid < 512) {
                int ix = tid ^ j;
                if (ix > tid) {
                    bool up = ((tid & sz) == 0);
                    int a = sel2[tid], c = sel2[ix];
                    if ((a > c) == up) { sel2[tid] = c; sel2[ix] = a; }
                }
            }
            __syncthreads();
        }
    }
    if (tid < Kk) {
        g_sel[b*Kk + tid]  = sel2[tid] >> 10;
        g_slot[b*Kk + tid] = sel2[tid] & 1023;
    }
}

// ---------------- gather: cached h rows + scores + spans -> out ----------------
__global__ void gather_kernel(const int* __restrict__ spans, float* __restrict__ out) {
    int j = blockIdx.x, b = blockIdx.y, tid = threadIdx.x;
    int t = b*Kk + j;
    int sid = g_sel[t], slot = g_slot[t];
    const float* src = g_Hc + (size_t)(b*CAP + slot)*Hh;
    float* dst = out + (size_t)t*Hh;
    for (int c = tid; c < Hh; c += blockDim.x) dst[c] = src[c];
    if (tid == 0) {
        size_t sc_base = (size_t)Bz*Kk*Hh;
        out[sc_base + t] = g_scores[b*Ss + sid];
        size_t sp_base = sc_base + (size_t)Bz*Kk;
        out[sp_base + (size_t)t*2]     = (float)spans[2*sid];
        out[sp_base + (size_t)t*2 + 1] = (float)spans[2*sid + 1];
    }
}

__global__ void fill_tail_kernel(float* out, long long begin, long long end) {
    long long i = begin + blockIdx.x * (long long)blockDim.x + threadIdx.x;
    if (i < end) out[i] = 0.0f;
}

extern "C" void kernel_launch(void* const* d_in, const int* in_sizes, int n_in,
                              void* d_out, int out_size) {
    const float* emb   = (const float*)d_in[0];
    const int*   mask  = (const int*)  d_in[1];
    const int*   spans = (const int*)  d_in[2];
    const float* wemb  = (const float*)d_in[3];
    const float* W1    = (const float*)d_in[4];
    const float* b1    = (const float*)d_in[5];
    const float* w_s   = (const float*)d_in[6];
    const float* b_s   = (const float*)d_in[7];
    float* out = (float*)d_out;
    (void)n_in; (void)in_sizes;

    cudaFuncSetAttribute(mma_main, cudaFuncAttributeMaxDynamicSharedMemorySize, DYNSMEM);

    // launch 1: R (+b1)
    r_kernel<<<MAXW, 256>>>(wemb, W1, b1);
    // launch 2: weight transpose -> fp8 (+ fused mask lengths)
    prep2_kernel<<<dim3(24, 25), dim3(32, 8)>>>(W1, mask);
    // launch 3: exact P and Q (128x128 tiles — proven fastest)
    pq_kernel<<<dim3(NBLK, (Bz*Nn)/128, 2), 256>>>(emb, W1);
    // launch 4 (ncu-captured): approx main GEMM (R15 version, 279us)
    mma_main<<<MTILES64, 256, DYNSMEM>>>(emb, spans, w_s, b_s);

    radix_kernel<<<Bz, 1024>>>(KEXT);
    filter_kernel<<<Bz, 1024>>>();

    // exact rescore (128x128 tiles — proven fastest)
    rescore_gemm<<<dim3(NBLK, (Bz*CAP)/128), 256>>>(emb, spans, W1 + WXY_OFF, w_s);
    rescore_reduce<<<(Bz*CAP + 255)/256, 256>>>(spans, b_s);

    final_select_kernel<<<Bz, CAP>>>();
    gather_kernel<<<dim3(Kk, Bz), 192>>>(spans, out);

    long long written = (long long)Bz*Kk*Hh + (long long)Bz*Kk + (long long)Bz*Kk*2;
    if ((long long)out_size > written) {
        long long extra = (long long)out_size - written;
        int blocks = (int)((extra + 255) / 256);
        fill_tail_kernel<<<blocks, 256>>>(out, written, (long long)out_size);
    }
}

// round 17
// speedup vs baseline: 1.1618x; 1.0251x over previous
#include <cuda_runtime.h>
#include <cuda_bf16.h>
#include <cuda_fp8.h>
#include <math.h>
#include <stdint.h>

#define Bz   2
#define Nn   1024
#define Hh   768
#define Ss   30285
#define Kk   409
#define MAXW 30
#define WD   20
#define NBLK 6
#define MTILES64 947              // ceil(Bz*Ss/64)
#define CAP  1024
#define KEXT (Kk + 512)
#define WXY_OFF (1536*768)
#define WW_ROW 2304
#define WBLK (768*768)

// ---- mma_main smem layout (bytes), fp8, M=64 ----
#define SAFB  784                 // A row stride bytes
#define A_BYTES (64*SAFB)         // 50176
#define SBB   80                  // B row stride bytes
#define BSTG_BYTES (128*SBB)      // 10240 per stage
#define NSTG  3
#define B_OFF A_BYTES
#define RED_OFF B_OFF             // red aliases B region (post-loop only)
#define XO_OFF (A_BYTES + NSTG*BSTG_BYTES)   // 80896
#define YO_OFF (XO_OFF + 256)
#define RO_OFF (YO_OFF + 256)
#define DYNSMEM (RO_OFF + 256)               // 81664  -> 2 CTAs/SM

#define ASCALE 8.0f
#define INVSCALE (1.0f/512.0f)

__device__ __forceinline__ float gelu_exact(float x) {
    return 0.5f * x * (1.0f + erff(x * 0.70710678118654752f));
}
__device__ __forceinline__ float gelu_fast(float x) {
    float arg = 0.7978845608028654f * (x + 0.044715f * x * x * x);
    float th;
    asm("tanh.approx.f32 %0, %1;" : "=f"(th) : "f"(arg));
    return 0.5f * x * (1.0f + th);
}
__device__ __forceinline__ uint32_t smem_u32(const void* p) {
    uint32_t a;
    asm("{ .reg .u64 t; cvta.to.shared.u64 t, %1; cvt.u32.u64 %0, t; }" : "=r"(a) : "l"(p));
    return a;
}
__device__ __forceinline__ void cp_async16(uint32_t dst, const void* src) {
    asm volatile("cp.async.cg.shared.global [%0], [%1], 16;" :: "r"(dst), "l"(src));
}
#define CP_COMMIT() asm volatile("cp.async.commit_group;" ::: "memory")
#define CP_WAIT0()  asm volatile("cp.async.wait_group 0;" ::: "memory")
#define CP_WAIT1()  asm volatile("cp.async.wait_group 1;" ::: "memory")

__device__ __forceinline__ void mma16832(float* c, const unsigned* a, const unsigned* b) {
    asm volatile("mma.sync.aligned.m16n8k32.row.col.f32.e4m3.e4m3.f32 "
        "{%0,%1,%2,%3}, {%4,%5,%6,%7}, {%8,%9}, {%0,%1,%2,%3};"
        : "+f"(c[0]), "+f"(c[1]), "+f"(c[2]), "+f"(c[3])
        : "r"(a[0]), "r"(a[1]), "r"(a[2]), "r"(a[3]), "r"(b[0]), "r"(b[1]));
}
__device__ __forceinline__ void ldsm4(unsigned* r, uint32_t addr) {
    asm volatile("ldmatrix.sync.aligned.m8n8.x4.shared.b16 {%0,%1,%2,%3}, [%4];"
        : "=r"(r[0]), "=r"(r[1]), "=r"(r[2]), "=r"(r[3]) : "r"(addr));
}

// ---------------- scratch ----------------
__device__ unsigned char g_W8[768*768]; // e4m3(Wxy * 64) transposed [n][k]
__device__ float    g_P [Bz*Nn*Hh];     // K-half 0
__device__ float    g_P2[Bz*Nn*Hh];     // K-half 1
__device__ float    g_Q [Bz*Nn*Hh];
__device__ float    g_Q2[Bz*Nn*Hh];
__device__ float    g_R[MAXW*Hh];
__device__ float    g_part2[NBLK*2*CAP];
__device__ float    g_Hc[(size_t)Bz*CAP*Hh];
__device__ float    g_scores[Bz*Ss];
__device__ unsigned g_keys[Bz*Ss];
__device__ int      g_len[Bz];
__device__ unsigned g_thr[Bz];
__device__ int      g_cand[Bz*CAP];
__device__ int      g_nc[Bz];
__device__ int      g_sel[Bz*Kk];
__device__ int      g_slot[Bz*Kk];

// ---------------- R[w] = width_emb[w] @ Ww + b1 ----------------
__global__ void r_kernel(const float* __restrict__ wemb,
                         const float* __restrict__ W1,
                         const float* __restrict__ b1) {
    int w = blockIdx.x;
    for (int c = threadIdx.x; c < Hh; c += blockDim.x) {
        float a = b1[c];
        #pragma unroll
        for (int j = 0; j < WD; j++) a += wemb[w*WD + j] * W1[(WW_ROW + j)*Hh + c];
        g_R[w*Hh + c] = a;
    }
}

// ---------------- Wxy -> transposed e4m3 (x64) + (fused) lengths ----------------
__global__ void prep2_kernel(const float* __restrict__ W1, const int* __restrict__ mask) {
    __shared__ float tile[32][33];
    int tx = threadIdx.x, ty = threadIdx.y;   // 32 x 8
    if (blockIdx.y == 24) {
        if (blockIdx.x >= Bz) return;
        __shared__ int red[256];
        int b = blockIdx.x, tid = ty*32 + tx;
        int p = 0;
        for (int i = tid; i < Nn; i += 256) p += mask[b*Nn + i];
        red[tid] = p; __syncthreads();
        for (int s = 128; s > 0; s >>= 1) { if (tid < s) red[tid] += red[tid+s]; __syncthreads(); }
        if (tid == 0) g_len[b] = red[0];
        return;
    }
    int kx = blockIdx.x * 32, ny = blockIdx.y * 32;
    #pragma unroll
    for (int i = 0; i < 32; i += 8)
        tile[ty + i][tx] = W1[WXY_OFF + (size_t)(kx + ty + i)*768 + ny + tx];
    __syncthreads();
    #pragma unroll
    for (int i = 0; i < 32; i += 8)
        g_W8[(size_t)(ny + ty + i)*768 + kx + tx] =
            __nv_cvt_float_to_fp8(tile[tx][ty + i] * 64.0f, __NV_SATFINITE, __NV_E4M3);
}

// ======= approx main GEMM: persistent-A e4m3 k32, M=64, warp-private B, unrolled =======
__global__ void __launch_bounds__(256, 2)
mma_main(const float* __restrict__ emb, const int* __restrict__ spans,
         const float* __restrict__ ws, const float* __restrict__ b_s) {
    extern __shared__ char sm[];
    const uint32_t sb0 = smem_u32(sm);
    int*   sXo = (int*)(sm + XO_OFF);
    int*   sYo = (int*)(sm + YO_OFF);
    int*   sRo = (int*)(sm + RO_OFF);
    float* red = (float*)(sm + RED_OFF);   // aliases B (post-loop only)

    const int tid = threadIdx.x, wid = tid >> 5, lane = tid & 31;
    const int m0 = blockIdx.x * 64;
    const int g = lane >> 2, t = lane & 3;
    const int warpN = wid;            // 8 warps x 16 n

    if (tid < 64) {
        int m = m0 + tid;
        int sid = -1, b = 0;
        if (m < Bz*Ss) { b = m / Ss; sid = m - b*Ss; }
        if (sid >= 0) {
            int s = spans[2*sid], e = spans[2*sid + 1];
            sXo[tid] = (b*Nn + s)*Hh;
            sYo[tid] = (b*Nn + e)*Hh;
            sRo[tid] = (e - s)*Hh;
        } else { sXo[tid] = -1; sYo[tid] = 0; sRo[tid] = 0; }
    }
    __syncthreads();

    // ---- A fill: ONCE per CTA, 64 x 768 e4m3(x*y*8); 4 threads per row ----
    {
        const int lr = tid >> 2;
        const int lk = (tid & 3) * 8;
        const int xoF = sXo[lr];
        const bool fvalid = xoF >= 0;
        const float* xp = emb + (fvalid ? xoF : 0);
        const float* yp = emb + (fvalid ? sYo[lr] : 0);
        char* arow = sm + lr*SAFB;
        #pragma unroll 4
        for (int c = 0; c < 24; c++) {
            const float* xs = xp + c*32 + lk;
            const float* ys = yp + c*32 + lk;
            float4 xa0 = *(const float4*)(xs);
            float4 xa1 = *(const float4*)(xs + 4);
            float4 ya0 = *(const float4*)(ys);
            float4 ya1 = *(const float4*)(ys + 4);
            float v[8] = {xa0.x*ya0.x, xa0.y*ya0.y, xa0.z*ya0.z, xa0.w*ya0.w,
                          xa1.x*ya1.x, xa1.y*ya1.y, xa1.z*ya1.z, xa1.w*ya1.w};
            unsigned short us[4];
            #pragma unroll
            for (int q = 0; q < 4; q++) {
                float2 f2 = fvalid ? make_float2(v[2*q]*ASCALE, v[2*q+1]*ASCALE)
                                   : make_float2(0.f, 0.f);
                us[q] = __nv_cvt_float2_to_fp8x2(f2, __NV_SATFINITE, __NV_E4M3);
            }
            uint2 u;
            u.x = (unsigned)us[0] | ((unsigned)us[1] << 16);
            u.y = (unsigned)us[2] | ((unsigned)us[3] << 16);
            *(uint2*)(arow + c*32 + lk) = u;
        }
    }
    __syncthreads();

    // ldsm lane addressing (hoisted bases)
    const int arow_l = lane & 15;
    const int acolB  = (lane >> 4) << 4;
    uint32_t aBase[4];
    #pragma unroll
    for (int mt = 0; mt < 4; mt++)
        aBase[mt] = sb0 + (mt*16 + arow_l)*SAFB + acolB;
    const uint32_t bBase4 = sb0 + B_OFF + (warpN*16 + (lane & 15))*SBB + ((lane >> 4) << 4);

    // per-warp B fill roles
    const int frow  = lane & 15;
    const int fhalf = (lane >> 4) * 32;
    const uint32_t fillDst = sb0 + B_OFF + (warpN*16 + frow)*SBB + fhalf;

    float pacc[4][2];
    #pragma unroll
    for (int i = 0; i < 4; i++) { pacc[i][0] = 0.f; pacc[i][1] = 0.f; }

    #pragma unroll 1
    for (int nblk = 0; nblk < NBLK; nblk++) {
        const int n0 = nblk * 128;
        const char* src0 = (const char*)g_W8 + (size_t)(n0 + warpN*16 + frow)*768 + fhalf;

        float acc[4][2][4];
        #pragma unroll
        for (int i = 0; i < 4; i++)
            #pragma unroll
            for (int j = 0; j < 2; j++)
                #pragma unroll
                for (int q = 0; q < 4; q++) acc[i][j][q] = 0.f;

        // per-warp prologue: chunks 0,1 in flight
        cp_async16(fillDst,      src0);
        cp_async16(fillDst + 16, src0 + 16);
        CP_COMMIT();
        cp_async16(fillDst + BSTG_BYTES,      src0 + 64);
        cp_async16(fillDst + BSTG_BYTES + 16, src0 + 80);
        CP_COMMIT();
        CP_WAIT1();
        __syncwarp();

        #pragma unroll
        for (int cc = 0; cc < 12; cc++) {
            const int p = cc % NSTG;
            if (cc + 2 < 12) {
                const int pn = (cc + 2) % NSTG;
                const char* src = src0 + (cc + 2)*64;
                cp_async16(fillDst + pn*BSTG_BYTES,      src);
                cp_async16(fillDst + pn*BSTG_BYTES + 16, src + 16);
                CP_COMMIT();
            }
            const uint32_t pOff = (uint32_t)(p*BSTG_BYTES);
            const uint32_t aOff = (uint32_t)(cc*64);
            #pragma unroll
            for (int s = 0; s < 2; s++) {
                const int koB = s*32;
                unsigned af[4][4], bq[4];
                #pragma unroll
                for (int mt = 0; mt < 4; mt++)
                    ldsm4(af[mt], aBase[mt] + aOff + koB);
                ldsm4(bq, bBase4 + pOff + koB);
                unsigned bf0[2] = {bq[0], bq[2]};
                unsigned bf1[2] = {bq[1], bq[3]};
                #pragma unroll
                for (int mt = 0; mt < 4; mt++) {
                    mma16832(acc[mt][0], af[mt], bf0);
                    mma16832(acc[mt][1], af[mt], bf1);
                }
            }
            if (cc + 2 < 12)     CP_WAIT1();
            else                 CP_WAIT0();
            __syncwarp();
        }

        // per-nblk epilogue (warp-local): accumulate h . ws
        float wv[2][2];
        #pragma unroll
        for (int nt = 0; nt < 2; nt++) {
            float2 Wv = *(const float2*)&ws[n0 + warpN*16 + nt*8 + 2*t];
            wv[nt][0] = Wv.x; wv[nt][1] = Wv.y;
        }
        #pragma unroll
        for (int mt = 0; mt < 4; mt++) {
            #pragma unroll
            for (int rr = 0; rr < 2; rr++) {
                int ml = mt*16 + g + rr*8;
                int xo2 = sXo[ml];
                if (xo2 >= 0) {
                    int yo2 = sYo[ml], ro2 = sRo[ml];
                    float p = 0.f;
                    #pragma unroll
                    for (int nt = 0; nt < 2; nt++) {
                        int n = n0 + warpN*16 + nt*8 + 2*t;
                        float2 Pa = *(const float2*)&g_P [xo2 + n];
                        float2 Pb = *(const float2*)&g_P2[xo2 + n];
                        float2 Qa = *(const float2*)&g_Q [yo2 + n];
                        float2 Qb = *(const float2*)&g_Q2[yo2 + n];
                        float2 Rv = *(const float2*)&g_R[ro2 + n];
                        float h0 = gelu_fast(acc[mt][nt][rr*2]*INVSCALE
                                             + (Pa.x + Pb.x) + (Qa.x + Qb.x) + Rv.x);
                        float h1 = gelu_fast(acc[mt][nt][rr*2+1]*INVSCALE
                                             + (Pa.y + Pb.y) + (Qa.y + Qb.y) + Rv.y);
                        p += h0*wv[nt][0] + h1*wv[nt][1];
                    }
                    pacc[mt][rr] += p;
                }
            }
        }
    }

    // all warps done with B region -> safe to alias red
    __syncthreads();
    #pragma unroll
    for (int mt = 0; mt < 4; mt++) {
        #pragma unroll
        for (int rr = 0; rr < 2; rr++) {
            float p = pacc[mt][rr];
            p += __shfl_xor_sync(0xffffffffu, p, 1);
            p += __shfl_xor_sync(0xffffffffu, p, 2);
            if (t == 0) {
                int ml = mt*16 + g + rr*8;
                red[ml*8 + warpN] = p;
            }
        }
    }
    __syncthreads();
    if (tid < 64) {
        int m = m0 + tid;
        if (m < Bz*Ss && sXo[tid] >= 0) {
            int b = m / Ss, sid = m - b*Ss;
            float sc = b_s[0];
            #pragma unroll
            for (int q = 0; q < 8; q++) sc += red[tid*8 + q];
            int e = spans[2*sid + 1];
            if (e >= g_len[b]) sc += -1000000.0f;
            g_scores[m] = sc;
            unsigned u = __float_as_uint(sc);
            g_keys[m] = (u & 0x80000000u) ? ~u : (u | 0x80000000u);
        }
    }
}

// ===== exact P/Q GEMM, 128x128 tiles, K-split x2 (z: weight*2 + khalf), 384 CTAs =====
__global__ void __launch_bounds__(256)
pq_kernel(const float* __restrict__ emb, const float* __restrict__ W1) {
    __shared__ float As[2][8][128];
    __shared__ float Bs[2][8][128];
    const int tid = threadIdx.x;
    const int n0 = blockIdx.x * 128;
    const int m0 = blockIdx.y * 128;
    const int wsel  = blockIdx.z >> 1;
    const int khalf = blockIdx.z & 1;
    const int kbeg = khalf * 384, kend = kbeg + 384;
    const float* W = W1 + (size_t)wsel * WBLK;
    float* C = wsel ? (khalf ? g_Q2 : g_Q) : (khalf ? g_P2 : g_P);

    const int tx = tid & 15, ty = tid >> 4;
    const int ar = tid >> 1, ac = (tid & 1) * 4;
    const int br = tid >> 5, bc = (tid & 31) * 4;
    const size_t Xo = (size_t)(m0 + ar)*Hh;

    unsigned long long acc[8][4];
    #pragma unroll
    for (int i = 0; i < 8; i++)
        #pragma unroll
        for (int j = 0; j < 4; j++) acc[i][j] = 0ULL;

    float4 xv = *(const float4*)(emb + Xo + kbeg + ac);
    float4 bv = *(const float4*)(W + (size_t)(kbeg + br)*Hh + n0 + bc);
    As[0][ac+0][ar] = xv.x; As[0][ac+1][ar] = xv.y;
    As[0][ac+2][ar] = xv.z; As[0][ac+3][ar] = xv.w;
    *(float4*)&Bs[0][br][bc] = bv;
    __syncthreads();

    for (int k0 = kbeg; k0 < kend; k0 += 8) {
        const int p = (k0 >> 3) & 1;
        const bool more = (k0 + 8) < kend;
        float4 nxv, nbv;
        if (more) {
            nxv = *(const float4*)(emb + Xo + k0 + 8 + ac);
            nbv = *(const float4*)(W + (size_t)(k0 + 8 + br)*Hh + n0 + bc);
        }
        #pragma unroll
        for (int kk = 0; kk < 8; kk++) {
            float4 a0 = *(float4*)&As[p][kk][ty*8];
            float4 a1 = *(float4*)&As[p][kk][ty*8 + 4];
            ulonglong2 b01 = *(ulonglong2*)&Bs[p][kk][tx*8];
            ulonglong2 b23 = *(ulonglong2*)&Bs[p][kk][tx*8 + 4];
            float av[8] = {a0.x,a0.y,a0.z,a0.w,a1.x,a1.y,a1.z,a1.w};
            unsigned long long bp[4] = {b01.x, b01.y, b23.x, b23.y};
            #pragma unroll
            for (int i = 0; i < 8; i++) {
                unsigned long long ad;
                asm("mov.b64 %0, {%1,%1};" : "=l"(ad) : "f"(av[i]));
                #pragma unroll
                for (int j = 0; j < 4; j++)
                    asm("fma.rn.f32x2 %0, %1, %2, %0;" : "+l"(acc[i][j]) : "l"(ad), "l"(bp[j]));
            }
        }
        if (more) {
            As[p^1][ac+0][ar] = nxv.x; As[p^1][ac+1][ar] = nxv.y;
            As[p^1][ac+2][ar] = nxv.z; As[p^1][ac+3][ar] = nxv.w;
            *(float4*)&Bs[p^1][br][bc] = nbv;
        }
        __syncthreads();
    }

    #pragma unroll
    for (int i = 0; i < 8; i++) {
        int m = m0 + ty*8 + i;
        float o[8];
        #pragma unroll
        for (int j = 0; j < 4; j++) {
            float lo, hi;
            asm("mov.b64 {%0,%1}, %2;" : "=f"(lo), "=f"(hi) : "l"(acc[i][j]));
            o[2*j] = lo; o[2*j+1] = hi;
        }
        int col0 = n0 + tx*8;
        *(float4*)&C[(size_t)m*Hh + col0]     = make_float4(o[0],o[1],o[2],o[3]);
        *(float4*)&C[(size_t)m*Hh + col0 + 4] = make_float4(o[4],o[5],o[6],o[7]);
    }
}

// ===== exact rescore GEMM, 128x128 tiles; h -> g_Hc, partials -> g_part2 =====
__global__ void __launch_bounds__(256)
rescore_gemm(const float* __restrict__ emb, const int* __restrict__ spans,
             const float* __restrict__ W, const float* __restrict__ ws) {
    __shared__ float As[2][8][128];
    __shared__ float Bs[2][8][128];
    __shared__ int sXo[128], sYo[128], sRo[128];
    __shared__ float red[128][17];

    const int tid = threadIdx.x;
    const int n0 = blockIdx.x * 128;
    const int m0 = blockIdx.y * 128;

    if (tid < 128) {
        int m = m0 + tid;
        int sid = -1, b = m >> 10;
        int j = m & (CAP - 1);
        if (b < Bz && j < g_nc[b]) sid = g_cand[m] - b*Ss;
        if (sid >= 0) {
            int s = spans[2*sid], e = spans[2*sid + 1];
            sXo[tid] = (b*Nn + s)*Hh;
            sYo[tid] = (b*Nn + e)*Hh;
            sRo[tid] = (e - s)*Hh;
        } else { sXo[tid] = -1; sYo[tid] = 0; sRo[tid] = 0; }
    }
    __syncthreads();

    const int tx = tid & 15, ty = tid >> 4;
    const int ar = tid >> 1, ac = (tid & 1) * 4;
    const int br = tid >> 5, bc = (tid & 31) * 4;

    const int xoRaw = sXo[ar];
    const int Xo = (xoRaw < 0) ? 0 : xoRaw;
    const int Yo = (xoRaw < 0) ? 0 : sYo[ar];

    unsigned long long acc[8][4];
    #pragma unroll
    for (int i = 0; i < 8; i++)
        #pragma unroll
        for (int j = 0; j < 4; j++) acc[i][j] = 0ULL;

    float4 xv = *(const float4*)(emb + Xo + ac);
    float4 yv = *(const float4*)(emb + Yo + ac);
    xv.x *= yv.x; xv.y *= yv.y; xv.z *= yv.z; xv.w *= yv.w;
    float4 bv = *(const float4*)(W + (size_t)br*Hh + n0 + bc);
    As[0][ac+0][ar] = xv.x; As[0][ac+1][ar] = xv.y;
    As[0][ac+2][ar] = xv.z; As[0][ac+3][ar] = xv.w;
    *(float4*)&Bs[0][br][bc] = bv;
    __syncthreads();

    for (int k0 = 0; k0 < Hh; k0 += 8) {
        const int p = (k0 >> 3) & 1;
        const bool more = (k0 + 8) < Hh;
        float4 nxv, nbv;
        if (more) {
            nxv = *(const float4*)(emb + Xo + k0 + 8 + ac);
            float4 yv2 = *(const float4*)(emb + Yo + k0 + 8 + ac);
            nxv.x *= yv2.x; nxv.y *= yv2.y; nxv.z *= yv2.z; nxv.w *= yv2.w;
            nbv = *(const float4*)(W + (size_t)(k0 + 8 + br)*Hh + n0 + bc);
        }
        #pragma unroll
        for (int kk = 0; kk < 8; kk++) {
            float4 a0 = *(float4*)&As[p][kk][ty*8];
            float4 a1 = *(float4*)&As[p][kk][ty*8 + 4];
            ulonglong2 b01 = *(ulonglong2*)&Bs[p][kk][tx*8];
            ulonglong2 b23 = *(ulonglong2*)&Bs[p][kk][tx*8 + 4];
            float av[8] = {a0.x,a0.y,a0.z,a0.w,a1.x,a1.y,a1.z,a1.w};
            unsigned long long bp[4] = {b01.x, b01.y, b23.x, b23.y};
            #pragma unroll
            for (int i = 0; i < 8; i++) {
                unsigned long long ad;
                asm("mov.b64 %0, {%1,%1};" : "=l"(ad) : "f"(av[i]));
                #pragma unroll
                for (int j = 0; j < 4; j++)
                    asm("fma.rn.f32x2 %0, %1, %2, %0;" : "+l"(acc[i][j]) : "l"(ad), "l"(bp[j]));
            }
        }
        if (more) {
            As[p^1][ac+0][ar] = nxv.x; As[p^1][ac+1][ar] = nxv.y;
            As[p^1][ac+2][ar] = nxv.z; As[p^1][ac+3][ar] = nxv.w;
            *(float4*)&Bs[p^1][br][bc] = nbv;
        }
        __syncthreads();
    }

    #pragma unroll
    for (int i = 0; i < 8; i++) {
        int r = ty*8 + i;
        int xo = sXo[r];
        int m = m0 + r;
        float o[8];
        #pragma unroll
        for (int j = 0; j < 4; j++) {
            float lo, hi;
            asm("mov.b64 {%0,%1}, %2;" : "=f"(lo), "=f"(hi) : "l"(acc[i][j]));
            o[2*j] = lo; o[2*j+1] = hi;
        }
        int col0 = n0 + tx*8;
        float partial = 0.f;
        if (xo >= 0) {
            int yo = sYo[r], ro = sRo[r];
            #pragma unroll
            for (int j = 0; j < 8; j++) {
                int c = col0 + j;
                float pre = o[j] + (g_P[xo + c] + g_P2[xo + c])
                                 + (g_Q[yo + c] + g_Q2[yo + c]) + g_R[ro + c];
                o[j] = gelu_exact(pre);
                partial += o[j] * ws[c];
            }
            *(float4*)&g_Hc[(size_t)m*Hh + col0]     = make_float4(o[0],o[1],o[2],o[3]);
            *(float4*)&g_Hc[(size_t)m*Hh + col0 + 4] = make_float4(o[4],o[5],o[6],o[7]);
        }
        red[r][tx] = partial;
    }
    __syncthreads();
    if (tid < 128) {
        float s = 0.f;
        #pragma unroll
        for (int j = 0; j < 16; j++) s += red[tid][j];
        if (sXo[tid] >= 0)
            g_part2[blockIdx.x*(2*CAP) + m0 + tid] = s;
    }
}

// ---------------- kth-largest key (approx, rank KEXT), 4-pass radix ----------------
__global__ void radix_kernel(int k) {
    __shared__ int hist[256];
    __shared__ unsigned s_prefix, s_mask;
    __shared__ int s_kneed;
    int b = blockIdx.x, tid = threadIdx.x;
    if (tid == 0) { s_prefix = 0u; s_mask = 0u; s_kneed = k; }
    __syncthreads();
    for (int shift = 24; shift >= 0; shift -= 8) {
        for (int i = tid; i < 256; i += blockDim.x) hist[i] = 0;
        __syncthreads();
        unsigned pm = s_mask, pf = s_prefix;
        for (int i = tid; i < Ss; i += blockDim.x) {
            unsigned key = g_keys[b*Ss + i];
            if ((key & pm) == pf) atomicAdd(&hist[(key >> shift) & 255], 1);
        }
        __syncthreads();
        if (tid == 0) {
            int cum = 0, kn = s_kneed;
            for (int bin = 255; bin >= 0; bin--) {
                int h = hist[bin];
                if (kn <= cum + h) {
                    s_prefix = pf | ((unsigned)bin << shift);
                    s_kneed = kn - cum;
                    s_mask  = pm | (0xFFu << shift);
                    break;
                }
                cum += h;
            }
        }
        __syncthreads();
    }
    if (tid == 0) g_thr[b] = s_prefix;
}

// ---------------- candidate filter ----------------
__global__ void filter_kernel() {
    __shared__ int cnt;
    int b = blockIdx.x, tid = threadIdx.x;
    if (tid == 0) cnt = 0;
    __syncthreads();
    unsigned T = g_thr[b];
    for (int i = tid; i < Ss; i += 1024) {
        if (g_keys[b*Ss + i] >= T) {
            int p = atomicAdd(&cnt, 1);
            if (p < CAP) g_cand[b*CAP + p] = b*Ss + i;
        }
    }
    __syncthreads();
    if (tid == 0) g_nc[b] = (cnt < CAP) ? cnt : CAP;
}

// ---------------- exact rescore assemble ----------------
__global__ void rescore_reduce(const int* __restrict__ spans,
                               const float* __restrict__ b_s) {
    int t = blockIdx.x * 256 + threadIdx.x;
    if (t >= Bz*CAP) return;
    int b = t >> 10, j = t & (CAP - 1);
    if (j >= g_nc[b]) return;
    int i = g_cand[t];
    float sc = b_s[0];
    #pragma unroll
    for (int nb = 0; nb < NBLK; nb++) sc += g_part2[nb*(2*CAP) + t];
    int sid = i - b*Ss;
    int e = spans[2*sid + 1];
    if (e >= g_len[b]) sc += -1000000.0f;
    g_scores[i] = sc;
    unsigned u = __float_as_uint(sc);
    g_keys[i] = (u & 0x80000000u) ? ~u : (u | 0x80000000u);
}

// ---------------- final exact selection (per batch); carries candidate slot ----------------
__global__ void final_select_kernel() {
    __shared__ unsigned long long comp[CAP];
    __shared__ int sel2[512];
    int b = blockIdx.x, tid = threadIdx.x;
    int nc = g_nc[b];
    if (tid < nc) {
        int i = g_cand[b*CAP + tid];
        unsigned key = g_keys[i];
        unsigned sid = (unsigned)(i - b*Ss);
        comp[tid] = ((unsigned long long)(~key) << 32) | ((unsigned long long)sid << 10)
                    | (unsigned long long)tid;
    } else {
        comp[tid] = 0xFFFFFFFFFFFFFFFFull;
    }
    __syncthreads();
    for (int sz = 2; sz <= CAP; sz <<= 1) {
        for (int j = sz >> 1; j > 0; j >>= 1) {
            int ix = tid ^ j;
            if (ix > tid) {
                bool up = ((tid & sz) == 0);
                unsigned long long a = comp[tid], c = comp[ix];
                if ((a > c) == up) { comp[tid] = c; comp[ix] = a; }
            }
            __syncthreads();
        }
    }
    if (tid < 512)
        sel2[tid] = (tid < Kk) ? (int)(unsigned)(comp[tid] & 0x1FFFFFFull) : 0x7FFFFFFF;
    __syncthreads();
    for (int sz = 2; sz <= 512; sz <<= 1) {
        for (int j = sz >> 1; j > 0; j >>= 1) {
            if (tid < 512) {
                int ix = tid ^ j;
                if (ix > tid) {
                    bool up = ((tid & sz) == 0);
                    int a = sel2[tid], c = sel2[ix];
                    if ((a > c) == up) { sel2[tid] = c; sel2[ix] = a; }
                }
            }
            __syncthreads();
        }
    }
    if (tid < Kk) {
        g_sel[b*Kk + tid]  = sel2[tid] >> 10;
        g_slot[b*Kk + tid] = sel2[tid] & 1023;
    }
}

// ---------------- gather: cached h rows + scores + spans -> out ----------------
__global__ void gather_kernel(const int* __restrict__ spans, float* __restrict__ out) {
    int j = blockIdx.x, b = blockIdx.y, tid = threadIdx.x;
    int t = b*Kk + j;
    int sid = g_sel[t], slot = g_slot[t];
    const float* src = g_Hc + (size_t)(b*CAP + slot)*Hh;
    float* dst = out + (size_t)t*Hh;
    for (int c = tid; c < Hh; c += blockDim.x) dst[c] = src[c];
    if (tid == 0) {
        size_t sc_base = (size_t)Bz*Kk*Hh;
        out[sc_base + t] = g_scores[b*Ss + sid];
        size_t sp_base = sc_base + (size_t)Bz*Kk;
        out[sp_base + (size_t)t*2]     = (float)spans[2*sid];
        out[sp_base + (size_t)t*2 + 1] = (float)spans[2*sid + 1];
    }
}

__global__ void fill_tail_kernel(float* out, long long begin, long long end) {
    long long i = begin + blockIdx.x * (long long)blockDim.x + threadIdx.x;
    if (i < end) out[i] = 0.0f;
}

extern "C" void kernel_launch(void* const* d_in, const int* in_sizes, int n_in,
                              void* d_out, int out_size) {
    const float* emb   = (const float*)d_in[0];
    const int*   mask  = (const int*)  d_in[1];
    const int*   spans = (const int*)  d_in[2];
    const float* wemb  = (const float*)d_in[3];
    const float* W1    = (const float*)d_in[4];
    const float* b1    = (const float*)d_in[5];
    const float* w_s   = (const float*)d_in[6];
    const float* b_s   = (const float*)d_in[7];
    float* out = (float*)d_out;
    (void)n_in; (void)in_sizes;

    cudaFuncSetAttribute(mma_main, cudaFuncAttributeMaxDynamicSharedMemorySize, DYNSMEM);

    // launch 1: R (+b1)
    r_kernel<<<MAXW, 256>>>(wemb, W1, b1);
    // launch 2: weight transpose -> fp8 (+ fused mask lengths)
    prep2_kernel<<<dim3(24, 25), dim3(32, 8)>>>(W1, mask);
    // launch 3: exact P and Q, K-split x2 (z: weight*2 + khalf), 384 CTAs
    pq_kernel<<<dim3(NBLK, (Bz*Nn)/128, 4), 256>>>(emb, W1);
    // launch 4 (ncu-captured): approx main GEMM (frozen at 277us)
    mma_main<<<MTILES64, 256, DYNSMEM>>>(emb, spans, w_s, b_s);

    radix_kernel<<<Bz, 1024>>>(KEXT);
    filter_kernel<<<Bz, 1024>>>();

    // exact rescore (128x128 tiles)
    rescore_gemm<<<dim3(NBLK, (Bz*CAP)/128), 256>>>(emb, spans, W1 + WXY_OFF, w_s);
    rescore_reduce<<<(Bz*CAP + 255)/256, 256>>>(spans, b_s);

    final_select_kernel<<<Bz, CAP>>>();
    gather_kernel<<<dim3(Kk, Bz), 192>>>(spans, out);

    long long written = (long long)Bz*Kk*Hh + (long long)Bz*Kk + (long long)Bz*Kk*2;
    if ((long long)out_size > written) {
        long long extra = (long long)out_size - written;
        int blocks = (int)((extra + 255) / 256);
        fill_tail_kernel<<<blocks, 256>>>(out, written, (long long)out_size);
    }
}